// round 9
// baseline (speedup 1.0000x reference)
#include <cuda_runtime.h>
#include <cuda_bf16.h>
#include <mma.h>

using namespace nvcuda;

// Problem shape (fixed by the benchmark)
constexpr int Bc = 64;    // batch
constexpr int Lc = 512;   // sequence length
constexpr int Dc = 256;   // channels in
constexpr int Fc = 256;   // channels out
constexpr int KTOT = 3 * Dc;   // im2col K = 768
constexpr int MT = 64;    // l-tile per block
constexpr int KS = 32;    // K slab staged in smem

constexpr int LDX = 264;  // xs leading dim (floats), mult of 8
constexpr int LDB = 264;
constexpr int LDC = 264;

// Scratch (no allocations allowed — device globals)
__device__ float g_h1[(size_t)Bc * Lc * Fc];     // 33.5 MB: conv1 output
__device__ int   g_ends[Bc * Lc];                // cumsum of durations

// ---------------------------------------------------------------------------
// Fused conv1d(k=3,same) -> +bias -> LayerNorm -> ReLU  (PASS 1 writes g_h1)
// PASS 2 additionally fuses the 256->1 linear + ReLU into dp_out.
// GEMM: M=MT (l positions), N=256 (f), K=768 (3 taps x 256 ch), tf32 wmma.
// ---------------------------------------------------------------------------
template <int PASS>
__global__ __launch_bounds__(256, 1) void conv_ln_kernel(
    const float* __restrict__ in,   // (B,L,C) row-major
    const float* __restrict__ w,    // (3,C,F) row-major == (768,256)
    const float* __restrict__ cb,   // conv bias (F)
    const float* __restrict__ gam,  // ln gamma (F)
    const float* __restrict__ bet,  // ln beta  (F)
    const float* __restrict__ linw, // (F) PASS 2 only
    const float* __restrict__ linb, // (1) PASS 2 only
    float* __restrict__ dp)         // (B,L)  PASS 2 only
{
    extern __shared__ __align__(16) float sm[];
    float* xs   = sm;                       // (MT+2) x LDX
    float* bs   = xs + (MT + 2) * LDX;      // KS x LDB
    float* cs   = bs + KS * LDB;            // MT x LDC
    float* p_cb = cs + MT * LDC;            // 256
    float* p_g  = p_cb + Fc;                // 256
    float* p_b  = p_g + Fc;                 // 256
    float* p_lw = p_b + Fc;                 // 256
    float* p_mu = p_lw + Fc;                // 64
    float* p_rs = p_mu + MT;                // 64

    const int tid = threadIdx.x;
    const int b   = blockIdx.y;
    const int l0  = blockIdx.x * MT;
    const float* inb = in + (size_t)b * Lc * Dc;

    // stage per-channel params
    for (int i = tid; i < Fc; i += 256) {
        p_cb[i] = cb[i];
        p_g[i]  = gam[i];
        p_b[i]  = bet[i];
        if (PASS == 2) p_lw[i] = linw[i];
    }

    // stage A: rows 0..MT+1 -> l = l0-1+row, zero-padded at batch edges, tf32
    for (int i = tid; i < (MT + 2) * (Dc / 4); i += 256) {
        int row = i / (Dc / 4), c4 = i % (Dc / 4);
        int l = l0 - 1 + row;
        float4 v = make_float4(0.f, 0.f, 0.f, 0.f);
        if (l >= 0 && l < Lc)
            v = reinterpret_cast<const float4*>(inb + (size_t)l * Dc)[c4];
        float* d = xs + row * LDX + c4 * 4;
        d[0] = wmma::__float_to_tf32(v.x);
        d[1] = wmma::__float_to_tf32(v.y);
        d[2] = wmma::__float_to_tf32(v.z);
        d[3] = wmma::__float_to_tf32(v.w);
    }

    const int wid = tid >> 5;
    const int wm = wid >> 2;          // 0..1 : 32 rows each
    const int wn = wid & 3;           // 0..3 : 64 cols each

    wmma::fragment<wmma::accumulator, 16, 16, 8, float> acc[2][4];
#pragma unroll
    for (int mi = 0; mi < 2; mi++)
#pragma unroll
        for (int ni = 0; ni < 4; ni++)
            wmma::fill_fragment(acc[mi][ni], 0.0f);

    __syncthreads();

    for (int kk = 0; kk < KTOT; kk += KS) {
        // stage B slab (KS x 256), tf32
        for (int i = tid; i < KS * (Fc / 4); i += 256) {
            int r = i / (Fc / 4), c4 = i % (Fc / 4);
            float4 v = reinterpret_cast<const float4*>(w + (size_t)(kk + r) * Fc)[c4];
            float* d = bs + r * LDB + c4 * 4;
            d[0] = wmma::__float_to_tf32(v.x);
            d[1] = wmma::__float_to_tf32(v.y);
            d[2] = wmma::__float_to_tf32(v.z);
            d[3] = wmma::__float_to_tf32(v.w);
        }
        __syncthreads();

        const int tap = kk >> 8;        // KS divides 256, so tap const per slab
        const int kc0 = kk & 255;
#pragma unroll
        for (int k8 = 0; k8 < KS; k8 += 8) {
            wmma::fragment<wmma::matrix_a, 16, 16, 8, wmma::precision::tf32, wmma::row_major> af[2];
            wmma::fragment<wmma::matrix_b, 16, 16, 8, wmma::precision::tf32, wmma::row_major> bf[4];
#pragma unroll
            for (int mi = 0; mi < 2; mi++)
                wmma::load_matrix_sync(af[mi], xs + (wm * 32 + mi * 16 + tap) * LDX + kc0 + k8, LDX);
#pragma unroll
            for (int ni = 0; ni < 4; ni++)
                wmma::load_matrix_sync(bf[ni], bs + k8 * LDB + wn * 64 + ni * 16, LDB);
#pragma unroll
            for (int mi = 0; mi < 2; mi++)
#pragma unroll
                for (int ni = 0; ni < 4; ni++)
                    wmma::mma_sync(acc[mi][ni], af[mi], bf[ni], acc[mi][ni]);
        }
        __syncthreads();
    }

    // spill accumulators to smem
#pragma unroll
    for (int mi = 0; mi < 2; mi++)
#pragma unroll
        for (int ni = 0; ni < 4; ni++)
            wmma::store_matrix_sync(cs + (wm * 32 + mi * 16) * LDC + wn * 64 + ni * 16,
                                    acc[mi][ni], LDC, wmma::mem_row_major);
    __syncthreads();

    // LayerNorm stats: 4 threads per row
    const int r = tid >> 2, sub = tid & 3;
    float s = 0.f, s2 = 0.f;
#pragma unroll 8
    for (int j = 0; j < 64; j++) {
        int f = sub * 64 + j;
        float v = cs[r * LDC + f] + p_cb[f];
        s += v; s2 += v * v;
    }
    s  += __shfl_xor_sync(0xffffffffu, s, 1);
    s  += __shfl_xor_sync(0xffffffffu, s, 2);
    s2 += __shfl_xor_sync(0xffffffffu, s2, 1);
    s2 += __shfl_xor_sync(0xffffffffu, s2, 2);
    float mu  = s * (1.0f / Fc);
    float var = s2 * (1.0f / Fc) - mu * mu;
    float rs  = rsqrtf(var + 1e-5f);

    if (PASS == 1) {
        if (sub == 0) { p_mu[r] = mu; p_rs[r] = rs; }
        __syncthreads();
        // coalesced normalized write to g_h1
        for (int i = tid; i < MT * (Fc / 4); i += 256) {
            int r2 = i / (Fc / 4), c4 = i % (Fc / 4);
            float m = p_mu[r2], q = p_rs[r2];
            const float* cp = cs + r2 * LDC + c4 * 4;
            float4 o;
            o.x = fmaxf((cp[0] + p_cb[c4 * 4 + 0] - m) * q * p_g[c4 * 4 + 0] + p_b[c4 * 4 + 0], 0.f);
            o.y = fmaxf((cp[1] + p_cb[c4 * 4 + 1] - m) * q * p_g[c4 * 4 + 1] + p_b[c4 * 4 + 1], 0.f);
            o.z = fmaxf((cp[2] + p_cb[c4 * 4 + 2] - m) * q * p_g[c4 * 4 + 2] + p_b[c4 * 4 + 2], 0.f);
            o.w = fmaxf((cp[3] + p_cb[c4 * 4 + 3] - m) * q * p_g[c4 * 4 + 3] + p_b[c4 * 4 + 3], 0.f);
            reinterpret_cast<float4*>(g_h1 + ((size_t)b * Lc + l0 + r2) * Fc)[c4] = o;
        }
    } else {
        // fuse LN + ReLU + 256->1 linear + ReLU
        float dpv = 0.f;
#pragma unroll 8
        for (int j = 0; j < 64; j++) {
            int f = sub * 64 + j;
            float v = cs[r * LDC + f] + p_cb[f];
            float y = fmaxf((v - mu) * rs * p_g[f] + p_b[f], 0.f);
            dpv += y * p_lw[f];
        }
        dpv += __shfl_xor_sync(0xffffffffu, dpv, 1);
        dpv += __shfl_xor_sync(0xffffffffu, dpv, 2);
        if (sub == 0)
            dp[(size_t)b * Lc + l0 + r] = fmaxf(dpv + linb[0], 0.f);
    }
}

// ---------------------------------------------------------------------------
// Per-batch inclusive scan of durations (512 elems)
// ---------------------------------------------------------------------------
__global__ __launch_bounds__(512) void scan_kernel(const int* __restrict__ tgt)
{
    __shared__ int s[Lc];
    int b = blockIdx.x, tid = threadIdx.x;
    s[tid] = tgt[b * Lc + tid];
    __syncthreads();
    for (int off = 1; off < Lc; off <<= 1) {
        int v = (tid >= off) ? s[tid - off] : 0;
        __syncthreads();
        s[tid] += v;
        __syncthreads();
    }
    g_ends[b * Lc + tid] = s[tid];
}

// ---------------------------------------------------------------------------
// Length regulate: binary-search gather, zero past total
// ---------------------------------------------------------------------------
__global__ __launch_bounds__(256) void gather_kernel(
    const float* __restrict__ x, float* __restrict__ out, int T)
{
    __shared__ int se[Lc];
    __shared__ int sidx[64];
    int b = blockIdx.y, t0 = blockIdx.x * 64, tid = threadIdx.x;

    for (int i = tid; i < Lc; i += 256) se[i] = g_ends[b * Lc + i];
    __syncthreads();
    int total = se[Lc - 1];
    if (tid < 64) {
        int t = t0 + tid;
        int lo = 0, hi = Lc;
        while (lo < hi) {
            int mid = (lo + hi) >> 1;
            if (se[mid] <= t) lo = mid + 1; else hi = mid;
        }
        sidx[tid] = (t < total) ? min(lo, Lc - 1) : -1;
    }
    __syncthreads();

    int tx = tid & 63, ty = tid >> 6;
    const float4* x4 = reinterpret_cast<const float4*>(x + (size_t)b * Lc * Dc);
    float4* o4 = reinterpret_cast<float4*>(out + ((size_t)b * T + t0) * Dc);
#pragma unroll
    for (int tt = ty; tt < 64; tt += 4) {
        int j = sidx[tt];
        float4 v = make_float4(0.f, 0.f, 0.f, 0.f);
        if (j >= 0) v = x4[j * (Dc / 4) + tx];
        o4[tt * (Dc / 4) + tx] = v;
    }
}

// ---------------------------------------------------------------------------
extern "C" void kernel_launch(void* const* d_in, const int* in_sizes, int n_in,
                              void* d_out, int out_size)
{
    // slot 2 is the scalar mel_max_length if present
    int off = (n_in >= 13 && in_sizes[2] == 1) ? 1 : 0;
    const float* x    = (const float*)d_in[0];
    const int*   tgt  = (const int*)d_in[1];
    const float* c1w  = (const float*)d_in[2 + off];
    const float* c1b  = (const float*)d_in[3 + off];
    const float* g1   = (const float*)d_in[4 + off];
    const float* b1   = (const float*)d_in[5 + off];
    const float* c2w  = (const float*)d_in[6 + off];
    const float* c2b  = (const float*)d_in[7 + off];
    const float* g2   = (const float*)d_in[8 + off];
    const float* b2   = (const float*)d_in[9 + off];
    const float* lw   = (const float*)d_in[10 + off];
    const float* lb   = (const float*)d_in[11 + off];

    float* out = (float*)d_out;
    int T = (out_size - Bc * Lc) / (Bc * Dc);   // 4096
    float* dp = out + (size_t)Bc * T * Dc;

    float* h1 = nullptr;
    cudaGetSymbolAddress((void**)&h1, g_h1);

    size_t smem_f = (size_t)(MT + 2) * LDX + (size_t)KS * LDB + (size_t)MT * LDC
                    + 4 * Fc + 2 * MT;
    size_t smem = smem_f * sizeof(float);
    cudaFuncSetAttribute(conv_ln_kernel<1>, cudaFuncAttributeMaxDynamicSharedMemorySize, (int)smem);
    cudaFuncSetAttribute(conv_ln_kernel<2>, cudaFuncAttributeMaxDynamicSharedMemorySize, (int)smem);

    scan_kernel<<<Bc, Lc>>>(tgt);
    conv_ln_kernel<1><<<dim3(Lc / MT, Bc), 256, smem>>>(x, c1w, c1b, g1, b1,
                                                        nullptr, nullptr, nullptr);
    conv_ln_kernel<2><<<dim3(Lc / MT, Bc), 256, smem>>>(h1, c2w, c2b, g2, b2,
                                                        lw, lb, dp);
    gather_kernel<<<dim3(T / 64, Bc), 256>>>(x, out, T);
}

// round 10
// speedup vs baseline: 1.1315x; 1.1315x over previous
#include <cuda_runtime.h>
#include <cuda_bf16.h>
#include <mma.h>

using namespace nvcuda;

// Problem shape (fixed by the benchmark)
constexpr int Bc = 64;    // batch
constexpr int Lc = 512;   // sequence length
constexpr int Dc = 256;   // channels in
constexpr int Fc = 256;   // channels out
constexpr int KTOT = 3 * Dc;   // im2col K = 768
constexpr int MT = 64;    // l-tile per block
constexpr int KS = 32;    // K slab staged in smem
constexpr int NSLAB = KTOT / KS;  // 24

constexpr int LDX = 264;  // xs leading dim (floats), mult of 8
constexpr int LDB = 264;
constexpr int LDC = 264;

// Scratch (no allocations allowed — device globals)
__device__ float g_h1[(size_t)Bc * Lc * Fc];     // 33.5 MB: conv1 output
__device__ int   g_ends[Bc * Lc];                // cumsum of durations

// ---------------------------------------------------------------------------
// Fused conv1d(k=3,same) -> +bias -> LayerNorm -> ReLU  (PASS 1 writes g_h1)
// PASS 2 additionally fuses the 256->1 linear + ReLU into dp_out.
// GEMM: M=MT, N=256, K=768, tf32 wmma, 2-stage pipelined B staging.
// ---------------------------------------------------------------------------
template <int PASS>
__global__ __launch_bounds__(256, 1) void conv_ln_kernel(
    const float* __restrict__ in,   // (B,L,C) row-major
    const float* __restrict__ w,    // (3,C,F) row-major == (768,256)
    const float* __restrict__ cb,   // conv bias (F)
    const float* __restrict__ gam,  // ln gamma (F)
    const float* __restrict__ bet,  // ln beta  (F)
    const float* __restrict__ linw, // (F) PASS 2 only
    const float* __restrict__ linb, // (1) PASS 2 only
    float* __restrict__ dp)         // (B,L)  PASS 2 only
{
    extern __shared__ __align__(16) float sm[];
    float* xs   = sm;                        // (MT+2) x LDX  (A tile; epilogue spill aliases this)
    float* bs   = xs + (MT + 2) * LDX;       // 2 x KS x LDB  (double-buffered B slab)
    float* p_cb = bs + 2 * KS * LDB;         // 256
    float* p_g  = p_cb + Fc;                 // 256
    float* p_b  = p_g + Fc;                  // 256
    float* p_lw = p_b + Fc;                  // 256
    float* p_mu = p_lw + Fc;                 // 64
    float* p_rs = p_mu + MT;                 // 64

    const int tid = threadIdx.x;
    const int b   = blockIdx.y;
    const int l0  = blockIdx.x * MT;
    const float* inb = in + (size_t)b * Lc * Dc;
    const float4* w4 = reinterpret_cast<const float4*>(w);

    // ---- register prefetch helpers: one KS x 256 slab = 8 float4 per thread
    float4 pf[8];
    auto prefetch = [&](int kk) {
        if (kk < KTOT) {
#pragma unroll
            for (int j = 0; j < 8; j++)
                pf[j] = w4[(size_t)kk * (Fc / 4) + tid + j * 256];
        }
    };
    auto commit = [&](float* buf) {
#pragma unroll
        for (int j = 0; j < 8; j++) {
            int idx = tid + j * 256;
            int r = idx >> 6, c4 = idx & 63;
            float* d = buf + r * LDB + c4 * 4;
            d[0] = wmma::__float_to_tf32(pf[j].x);
            d[1] = wmma::__float_to_tf32(pf[j].y);
            d[2] = wmma::__float_to_tf32(pf[j].z);
            d[3] = wmma::__float_to_tf32(pf[j].w);
        }
    };

    // issue slab-0 loads first so they fly while we stage A
    prefetch(0);

    // stage per-channel params
    for (int i = tid; i < Fc; i += 256) {
        p_cb[i] = cb[i];
        p_g[i]  = gam[i];
        p_b[i]  = bet[i];
        if (PASS == 2) p_lw[i] = linw[i];
    }

    // stage A: rows 0..MT+1 -> l = l0-1+row, zero-padded at edges, tf32
    for (int i = tid; i < (MT + 2) * (Dc / 4); i += 256) {
        int row = i / (Dc / 4), c4 = i % (Dc / 4);
        int l = l0 - 1 + row;
        float4 v = make_float4(0.f, 0.f, 0.f, 0.f);
        if (l >= 0 && l < Lc)
            v = reinterpret_cast<const float4*>(inb + (size_t)l * Dc)[c4];
        float* d = xs + row * LDX + c4 * 4;
        d[0] = wmma::__float_to_tf32(v.x);
        d[1] = wmma::__float_to_tf32(v.y);
        d[2] = wmma::__float_to_tf32(v.z);
        d[3] = wmma::__float_to_tf32(v.w);
    }

    const int wid = tid >> 5;
    const int wm = wid >> 2;          // 0..1 : 32 rows each
    const int wn = wid & 3;           // 0..3 : 64 cols each

    wmma::fragment<wmma::accumulator, 16, 16, 8, float> acc[2][4];
#pragma unroll
    for (int mi = 0; mi < 2; mi++)
#pragma unroll
        for (int ni = 0; ni < 4; ni++)
            wmma::fill_fragment(acc[mi][ni], 0.0f);

    // prologue: commit slab0, start slab1 loads
    commit(bs);
    prefetch(KS);
    __syncthreads();

    // ---- main pipelined loop: 1 barrier per slab ----
    for (int it = 0; it < NSLAB; ++it) {
        const int kk = it * KS;
        const float* buf = bs + (it & 1) * (KS * LDB);
        const int tap = kk >> 8;       // KS divides 256 -> constant per slab
        const int kc0 = kk & 255;

#pragma unroll
        for (int k8 = 0; k8 < KS; k8 += 8) {
            wmma::fragment<wmma::matrix_a, 16, 16, 8, wmma::precision::tf32, wmma::row_major> af[2];
            wmma::fragment<wmma::matrix_b, 16, 16, 8, wmma::precision::tf32, wmma::row_major> bf[4];
#pragma unroll
            for (int mi = 0; mi < 2; mi++)
                wmma::load_matrix_sync(af[mi], xs + (wm * 32 + mi * 16 + tap) * LDX + kc0 + k8, LDX);
#pragma unroll
            for (int ni = 0; ni < 4; ni++)
                wmma::load_matrix_sync(bf[ni], buf + k8 * LDB + wn * 64 + ni * 16, LDB);
#pragma unroll
            for (int mi = 0; mi < 2; mi++)
#pragma unroll
                for (int ni = 0; ni < 4; ni++)
                    wmma::mma_sync(acc[mi][ni], af[mi], bf[ni], acc[mi][ni]);
        }

        if (it + 1 < NSLAB) {
            commit(bs + ((it + 1) & 1) * (KS * LDB));   // regs hold slab it+1
            prefetch((it + 2) * KS);                    // start slab it+2 loads
        }
        __syncthreads();
    }

    // ---- epilogue: spill accumulators into cs (aliases xs; A tile is dead)
    float* cs = xs;
#pragma unroll
    for (int mi = 0; mi < 2; mi++)
#pragma unroll
        for (int ni = 0; ni < 4; ni++)
            wmma::store_matrix_sync(cs + (wm * 32 + mi * 16) * LDC + wn * 64 + ni * 16,
                                    acc[mi][ni], LDC, wmma::mem_row_major);
    __syncthreads();

    // LayerNorm stats: 4 threads per row
    const int r = tid >> 2, sub = tid & 3;
    float s = 0.f, s2 = 0.f;
#pragma unroll 8
    for (int j = 0; j < 64; j++) {
        int f = sub * 64 + j;
        float v = cs[r * LDC + f] + p_cb[f];
        s += v; s2 += v * v;
    }
    s  += __shfl_xor_sync(0xffffffffu, s, 1);
    s  += __shfl_xor_sync(0xffffffffu, s, 2);
    s2 += __shfl_xor_sync(0xffffffffu, s2, 1);
    s2 += __shfl_xor_sync(0xffffffffu, s2, 2);
    float mu  = s * (1.0f / Fc);
    float var = s2 * (1.0f / Fc) - mu * mu;
    float rs  = rsqrtf(var + 1e-5f);

    if (PASS == 1) {
        if (sub == 0) { p_mu[r] = mu; p_rs[r] = rs; }
        __syncthreads();
        // coalesced normalized write to g_h1
        for (int i = tid; i < MT * (Fc / 4); i += 256) {
            int r2 = i / (Fc / 4), c4 = i % (Fc / 4);
            float m = p_mu[r2], q = p_rs[r2];
            const float* cp = cs + r2 * LDC + c4 * 4;
            float4 o;
            o.x = fmaxf((cp[0] + p_cb[c4 * 4 + 0] - m) * q * p_g[c4 * 4 + 0] + p_b[c4 * 4 + 0], 0.f);
            o.y = fmaxf((cp[1] + p_cb[c4 * 4 + 1] - m) * q * p_g[c4 * 4 + 1] + p_b[c4 * 4 + 1], 0.f);
            o.z = fmaxf((cp[2] + p_cb[c4 * 4 + 2] - m) * q * p_g[c4 * 4 + 2] + p_b[c4 * 4 + 2], 0.f);
            o.w = fmaxf((cp[3] + p_cb[c4 * 4 + 3] - m) * q * p_g[c4 * 4 + 3] + p_b[c4 * 4 + 3], 0.f);
            reinterpret_cast<float4*>(g_h1 + ((size_t)b * Lc + l0 + r2) * Fc)[c4] = o;
        }
    } else {
        // fuse LN + ReLU + 256->1 linear + ReLU
        float dpv = 0.f;
#pragma unroll 8
        for (int j = 0; j < 64; j++) {
            int f = sub * 64 + j;
            float v = cs[r * LDC + f] + p_cb[f];
            float y = fmaxf((v - mu) * rs * p_g[f] + p_b[f], 0.f);
            dpv += y * p_lw[f];
        }
        dpv += __shfl_xor_sync(0xffffffffu, dpv, 1);
        dpv += __shfl_xor_sync(0xffffffffu, dpv, 2);
        if (sub == 0)
            dp[(size_t)b * Lc + l0 + r] = fmaxf(dpv + linb[0], 0.f);
    }
}

// ---------------------------------------------------------------------------
// Per-batch inclusive scan of durations (512 elems)
// ---------------------------------------------------------------------------
__global__ __launch_bounds__(512) void scan_kernel(const int* __restrict__ tgt)
{
    __shared__ int s[Lc];
    int b = blockIdx.x, tid = threadIdx.x;
    s[tid] = tgt[b * Lc + tid];
    __syncthreads();
    for (int off = 1; off < Lc; off <<= 1) {
        int v = (tid >= off) ? s[tid - off] : 0;
        __syncthreads();
        s[tid] += v;
        __syncthreads();
    }
    g_ends[b * Lc + tid] = s[tid];
}

// ---------------------------------------------------------------------------
// Length regulate: binary-search gather, zero past total. Streaming stores.
// ---------------------------------------------------------------------------
__global__ __launch_bounds__(256) void gather_kernel(
    const float* __restrict__ x, float* __restrict__ out, int T)
{
    __shared__ int se[Lc];
    __shared__ int sidx[64];
    int b = blockIdx.y, t0 = blockIdx.x * 64, tid = threadIdx.x;

    for (int i = tid; i < Lc; i += 256) se[i] = g_ends[b * Lc + i];
    __syncthreads();
    int total = se[Lc - 1];
    if (tid < 64) {
        int t = t0 + tid;
        int lo = 0, hi = Lc;
        while (lo < hi) {
            int mid = (lo + hi) >> 1;
            if (se[mid] <= t) lo = mid + 1; else hi = mid;
        }
        sidx[tid] = (t < total) ? min(lo, Lc - 1) : -1;
    }
    __syncthreads();

    int tx = tid & 63, ty = tid >> 6;
    const float4* x4 = reinterpret_cast<const float4*>(x + (size_t)b * Lc * Dc);
    float4* o4 = reinterpret_cast<float4*>(out + ((size_t)b * T + t0) * Dc);
#pragma unroll
    for (int tt = ty; tt < 64; tt += 4) {
        int j = sidx[tt];
        float4 v = make_float4(0.f, 0.f, 0.f, 0.f);
        if (j >= 0) v = x4[j * (Dc / 4) + tx];
        __stcs(&o4[tt * (Dc / 4) + tx], v);   // streaming: write-once, skip L2 allocate
    }
}

// ---------------------------------------------------------------------------
extern "C" void kernel_launch(void* const* d_in, const int* in_sizes, int n_in,
                              void* d_out, int out_size)
{
    // slot 2 is the scalar mel_max_length if present
    int off = (n_in >= 13 && in_sizes[2] == 1) ? 1 : 0;
    const float* x    = (const float*)d_in[0];
    const int*   tgt  = (const int*)d_in[1];
    const float* c1w  = (const float*)d_in[2 + off];
    const float* c1b  = (const float*)d_in[3 + off];
    const float* g1   = (const float*)d_in[4 + off];
    const float* b1   = (const float*)d_in[5 + off];
    const float* c2w  = (const float*)d_in[6 + off];
    const float* c2b  = (const float*)d_in[7 + off];
    const float* g2   = (const float*)d_in[8 + off];
    const float* b2   = (const float*)d_in[9 + off];
    const float* lw   = (const float*)d_in[10 + off];
    const float* lb   = (const float*)d_in[11 + off];

    float* out = (float*)d_out;
    int T = (out_size - Bc * Lc) / (Bc * Dc);   // 4096
    float* dp = out + (size_t)Bc * T * Dc;

    float* h1 = nullptr;
    cudaGetSymbolAddress((void**)&h1, g_h1);

    size_t smem_f = (size_t)(MT + 2) * LDX + (size_t)2 * KS * LDB
                    + 4 * Fc + 2 * MT;
    size_t smem = smem_f * sizeof(float);
    cudaFuncSetAttribute(conv_ln_kernel<1>, cudaFuncAttributeMaxDynamicSharedMemorySize, (int)smem);
    cudaFuncSetAttribute(conv_ln_kernel<2>, cudaFuncAttributeMaxDynamicSharedMemorySize, (int)smem);

    scan_kernel<<<Bc, Lc>>>(tgt);
    conv_ln_kernel<1><<<dim3(Lc / MT, Bc), 256, smem>>>(x, c1w, c1b, g1, b1,
                                                        nullptr, nullptr, nullptr);
    conv_ln_kernel<2><<<dim3(Lc / MT, Bc), 256, smem>>>(h1, c2w, c2b, g2, b2,
                                                        lw, lb, dp);
    gather_kernel<<<dim3(T / 64, Bc), 256>>>(x, out, T);
}

// round 14
// speedup vs baseline: 1.2789x; 1.1303x over previous
#include <cuda_runtime.h>
#include <mma.h>
#include <cstdint>

using namespace nvcuda;

// Problem shape (fixed)
constexpr int Bc = 64, Lc = 512, Dc = 256, Fc = 256;
constexpr int MT = 64;            // output rows per CTA
constexpr int KS = 32;            // K slab
constexpr int NSLAB = 768 / KS;   // 24
constexpr int LDA = 40;           // A slab stride (floats)
constexpr int LDB = 264;          // B slab stride
constexpr int LDC = 264;          // epilogue bounce stride

constexpr int ABUF = MT * LDA;            // 2560 floats per A buffer
constexpr int BBUF = KS * LDB;            // 8448 floats per B buffer
constexpr int OFF_B = 2 * ABUF;           // 5120
constexpr int OFF_P = OFF_B + 2 * BBUF;   // 22016
constexpr int SMEMF = OFF_P + 1152;       // 23168 floats = 92672 B (2 CTAs/SM)

// Device scratch (no allocations allowed)
__device__ float g_h1[(size_t)Bc * Lc * Fc];   // conv1 out, tf32-rounded
__device__ float g_xr[(size_t)Bc * Lc * Dc];   // x pre-rounded to tf32
__device__ float g_w[2][768 * Fc];             // weights pre-rounded to tf32
__device__ int   g_ends[Bc * Lc];
__device__ __align__(16) float g_zero[8];      // zero-initialized

// ---------------------------------------------------------------- helpers
__device__ __forceinline__ uint32_t smem_u32(const void* p) {
    uint32_t a;
    asm("{ .reg .u64 t; cvta.to.shared.u64 t, %1; cvt.u32.u64 %0, t; }" : "=r"(a) : "l"(p));
    return a;
}
__device__ __forceinline__ float to_tf32(float x) {
    float r; asm("cvt.rna.tf32.f32 %0, %1;" : "=f"(r) : "f"(x)); return r;
}
__device__ __forceinline__ void cpa16(uint32_t dst, const void* src) {
    asm volatile("cp.async.ca.shared.global [%0], [%1], 16;" :: "r"(dst), "l"(src));
}
#define CPA_COMMIT() asm volatile("cp.async.commit_group;" ::: "memory")
#define CPA_WAIT(n)  asm volatile("cp.async.wait_group %0;" :: "n"(n) : "memory")

// ---------------------------------------------------------------------------
// Prep: round weights / x to tf32 once (keeps GEMM staging cvt-free)
// ---------------------------------------------------------------------------
__global__ void cvt_w(const float* __restrict__ w1, const float* __restrict__ w2)
{
    int i = blockIdx.x * 256 + threadIdx.x;            // float4 idx, 49152 per w
    const float4* s = (const float4*)(blockIdx.y ? w2 : w1);
    float4 v = s[i];
    v.x = to_tf32(v.x); v.y = to_tf32(v.y); v.z = to_tf32(v.z); v.w = to_tf32(v.w);
    ((float4*)g_w[blockIdx.y])[i] = v;
}
__global__ void cvt_x(const float* __restrict__ x)
{
    size_t i = (size_t)blockIdx.x * 256 + threadIdx.x; // float4 idx, 2097152
    float4 v = ((const float4*)x)[i];
    v.x = to_tf32(v.x); v.y = to_tf32(v.y); v.z = to_tf32(v.z); v.w = to_tf32(v.w);
    ((float4*)g_xr)[i] = v;
}

// ---------------------------------------------------------------------------
// Fused conv1d(k=3,same) -> bias -> LN -> ReLU (PASS1 -> g_h1, tf32-rounded)
// PASS2 fuses the 256->1 linear + ReLU into dp.
// tf32 wmma, cp.async double-buffered slabs, 2 CTAs/SM.
// ---------------------------------------------------------------------------
template <int PASS>
__global__ __launch_bounds__(256, 2) void conv_wmma(
    const float* __restrict__ in,   // (B,L,256) already tf32-rounded
    const float* __restrict__ w,    // (768,256) already tf32-rounded
    const float* __restrict__ cb,
    const float* __restrict__ gam,
    const float* __restrict__ bet,
    const float* __restrict__ linw,
    const float* __restrict__ linb,
    float* __restrict__ dp)
{
    extern __shared__ __align__(16) float smf[];
    float* p_cb = smf + OFF_P;
    float* p_g  = p_cb + 256;
    float* p_b  = p_g + 256;
    float* p_lw = p_b + 256;
    float* p_mu = p_lw + 256;   // 64
    float* p_rs = p_mu + 64;    // 64

    const uint32_t smA = smem_u32(smf);
    const uint32_t smB = smA + OFF_B * 4;

    const int tid = threadIdx.x;
    const int b   = blockIdx.y;
    const int l0  = blockIdx.x * MT;
    const float* inb = in + (size_t)b * Lc * Dc;

    // ---- slab staging via cp.async (A: 64x32 with tap baked in; B: 32x256)
    auto stage = [&](int slab, int bufi) {
        const int tap = slab >> 3;            // KS=32 -> 8 slabs per tap
        const int kc0 = (slab & 7) * KS;
        const uint32_t ab = smA + (uint32_t)bufi * (ABUF * 4);
#pragma unroll
        for (int t = 0; t < 2; t++) {         // 512 chunks of 16B
            int i = tid + t * 256;
            int r = i >> 3, c = i & 7;
            int l = l0 + r - 1 + tap;
            const void* src = (l >= 0 && l < Lc)
                ? (const void*)(inb + (size_t)l * Dc + kc0 + c * 4)
                : (const void*)g_zero;
            cpa16(ab + (uint32_t)(r * LDA + c * 4) * 4, src);
        }
        const uint32_t bb = smB + (uint32_t)bufi * (BBUF * 4);
        const float* wsrc = w + (size_t)slab * KS * Fc;
#pragma unroll
        for (int t = 0; t < 8; t++) {         // 2048 chunks of 16B
            int i = tid + t * 256;
            int r = i >> 6, c = i & 63;
            cpa16(bb + (uint32_t)(r * LDB + c * 4) * 4, wsrc + (size_t)r * Fc + c * 4);
        }
    };

    // params (plain loads)
    for (int i = tid; i < Fc; i += 256) {
        p_cb[i] = cb[i]; p_g[i] = gam[i]; p_b[i] = bet[i];
        if (PASS == 2) p_lw[i] = linw[i];
    }

    const int wid = tid >> 5;
    const int wm = wid >> 2;          // 0..1 : 32 rows
    const int wn = wid & 3;           // 0..3 : 64 cols

    wmma::fragment<wmma::accumulator, 16, 16, 8, float> acc[2][4];
#pragma unroll
    for (int mi = 0; mi < 2; mi++)
#pragma unroll
        for (int ni = 0; ni < 4; ni++)
            wmma::fill_fragment(acc[mi][ni], 0.0f);

    stage(0, 0);
    CPA_COMMIT();

    for (int it = 0; it < NSLAB; ++it) {
        if (it + 1 < NSLAB) {
            stage(it + 1, (it + 1) & 1);
            CPA_COMMIT();
            CPA_WAIT(1);               // slab `it` landed; `it+1` in flight
        } else {
            CPA_WAIT(0);
        }
        __syncthreads();

        const float* As = smf + (it & 1) * ABUF;
        const float* Bs = smf + OFF_B + (it & 1) * BBUF;
#pragma unroll
        for (int k8 = 0; k8 < KS; k8 += 8) {
            wmma::fragment<wmma::matrix_a, 16, 16, 8, wmma::precision::tf32, wmma::row_major> af[2];
            wmma::fragment<wmma::matrix_b, 16, 16, 8, wmma::precision::tf32, wmma::row_major> bf[4];
#pragma unroll
            for (int mi = 0; mi < 2; mi++)
                wmma::load_matrix_sync(af[mi], As + (wm * 32 + mi * 16) * LDA + k8, LDA);
#pragma unroll
            for (int ni = 0; ni < 4; ni++)
                wmma::load_matrix_sync(bf[ni], Bs + k8 * LDB + wn * 64 + ni * 16, LDB);
#pragma unroll
            for (int mi = 0; mi < 2; mi++)
#pragma unroll
                for (int ni = 0; ni < 4; ni++)
                    wmma::mma_sync(acc[mi][ni], af[mi], bf[ni], acc[mi][ni]);
        }
        __syncthreads();
    }

    // ---- epilogue: spill into cs (aliases slab buffers; dead now)
    float* cs = smf;
#pragma unroll
    for (int mi = 0; mi < 2; mi++)
#pragma unroll
        for (int ni = 0; ni < 4; ni++)
            wmma::store_matrix_sync(cs + (wm * 32 + mi * 16) * LDC + wn * 64 + ni * 16,
                                    acc[mi][ni], LDC, wmma::mem_row_major);
    __syncthreads();

    // LayerNorm stats: 4 threads per row
    const int r = tid >> 2, sub = tid & 3;
    float s = 0.f, s2 = 0.f;
#pragma unroll 8
    for (int j = 0; j < 64; j++) {
        int f = sub * 64 + j;
        float v = cs[r * LDC + f] + p_cb[f];
        s += v; s2 += v * v;
    }
    s  += __shfl_xor_sync(0xffffffffu, s, 1);
    s  += __shfl_xor_sync(0xffffffffu, s, 2);
    s2 += __shfl_xor_sync(0xffffffffu, s2, 1);
    s2 += __shfl_xor_sync(0xffffffffu, s2, 2);
    float mu  = s * (1.0f / Fc);
    float var = s2 * (1.0f / Fc) - mu * mu;
    float rs  = rsqrtf(var + 1e-5f);

    if (PASS == 1) {
        if (sub == 0) { p_mu[r] = mu; p_rs[r] = rs; }
        __syncthreads();
        // normalized + ReLU, tf32-rounded (it is conv2's A operand)
        for (int i = tid; i < MT * (Fc / 4); i += 256) {
            int r2 = i >> 6, c = (i & 63) << 2;
            float m = p_mu[r2], q = p_rs[r2];
            const float* cp = cs + r2 * LDC + c;
            float4 o;
            o.x = to_tf32(fmaxf((cp[0] + p_cb[c + 0] - m) * q * p_g[c + 0] + p_b[c + 0], 0.f));
            o.y = to_tf32(fmaxf((cp[1] + p_cb[c + 1] - m) * q * p_g[c + 1] + p_b[c + 1], 0.f));
            o.z = to_tf32(fmaxf((cp[2] + p_cb[c + 2] - m) * q * p_g[c + 2] + p_b[c + 2], 0.f));
            o.w = to_tf32(fmaxf((cp[3] + p_cb[c + 3] - m) * q * p_g[c + 3] + p_b[c + 3], 0.f));
            *(float4*)(g_h1 + ((size_t)b * Lc + l0 + r2) * Fc + c) = o;
        }
    } else {
        // fuse LN + ReLU + 256->1 linear + ReLU
        float dpv = 0.f;
#pragma unroll 8
        for (int j = 0; j < 64; j++) {
            int f = sub * 64 + j;
            float v = cs[r * LDC + f] + p_cb[f];
            float y = fmaxf((v - mu) * rs * p_g[f] + p_b[f], 0.f);
            dpv += y * p_lw[f];
        }
        dpv += __shfl_xor_sync(0xffffffffu, dpv, 1);
        dpv += __shfl_xor_sync(0xffffffffu, dpv, 2);
        if (sub == 0)
            dp[(size_t)b * Lc + l0 + r] = fmaxf(dpv + linb[0], 0.f);
    }
}

// ---------------------------------------------------------------------------
// Per-batch inclusive scan of durations (512 elems)
// ---------------------------------------------------------------------------
__global__ __launch_bounds__(512) void scan_kernel(const int* __restrict__ tgt)
{
    __shared__ int s[Lc];
    int b = blockIdx.x, tid = threadIdx.x;
    s[tid] = tgt[b * Lc + tid];
    __syncthreads();
    for (int off = 1; off < Lc; off <<= 1) {
        int v = (tid >= off) ? s[tid - off] : 0;
        __syncthreads();
        s[tid] += v;
        __syncthreads();
    }
    g_ends[b * Lc + tid] = s[tid];
}

// ---------------------------------------------------------------------------
// Length regulate: binary-search gather, zero past total. Streaming stores.
// ---------------------------------------------------------------------------
__global__ __launch_bounds__(256) void gather_kernel(
    const float* __restrict__ x, float* __restrict__ out, int T)
{
    __shared__ int se[Lc];
    __shared__ int sidx[64];
    int b = blockIdx.y, t0 = blockIdx.x * 64, tid = threadIdx.x;

    for (int i = tid; i < Lc; i += 256) se[i] = g_ends[b * Lc + i];
    __syncthreads();
    int total = se[Lc - 1];
    if (tid < 64) {
        int t = t0 + tid;
        int lo = 0, hi = Lc;
        while (lo < hi) {
            int mid = (lo + hi) >> 1;
            if (se[mid] <= t) lo = mid + 1; else hi = mid;
        }
        sidx[tid] = (t < total) ? min(lo, Lc - 1) : -1;
    }
    __syncthreads();

    int tx = tid & 63, ty = tid >> 6;
    const float4* x4 = reinterpret_cast<const float4*>(x + (size_t)b * Lc * Dc);
    float4* o4 = reinterpret_cast<float4*>(out + ((size_t)b * T + t0) * Dc);
#pragma unroll
    for (int tt = ty; tt < 64; tt += 4) {
        int j = sidx[tt];
        float4 v = make_float4(0.f, 0.f, 0.f, 0.f);
        if (j >= 0) v = x4[j * (Dc / 4) + tx];
        __stcs(&o4[tt * (Dc / 4) + tx], v);
    }
}

// ---------------------------------------------------------------------------
extern "C" void kernel_launch(void* const* d_in, const int* in_sizes, int n_in,
                              void* d_out, int out_size)
{
    int off = (n_in >= 13 && in_sizes[2] == 1) ? 1 : 0;
    const float* x   = (const float*)d_in[0];
    const int*   tgt = (const int*)d_in[1];
    const float* c1w = (const float*)d_in[2 + off];
    const float* c1b = (const float*)d_in[3 + off];
    const float* g1  = (const float*)d_in[4 + off];
    const float* b1  = (const float*)d_in[5 + off];
    const float* c2w = (const float*)d_in[6 + off];
    const float* c2b = (const float*)d_in[7 + off];
    const float* g2  = (const float*)d_in[8 + off];
    const float* b2  = (const float*)d_in[9 + off];
    const float* lw  = (const float*)d_in[10 + off];
    const float* lb  = (const float*)d_in[11 + off];

    float* out = (float*)d_out;
    int T = (out_size - Bc * Lc) / (Bc * Dc);   // 4096
    float* dp = out + (size_t)Bc * T * Dc;

    float *h1 = nullptr, *xr = nullptr, *wv = nullptr;
    cudaGetSymbolAddress((void**)&h1, g_h1);
    cudaGetSymbolAddress((void**)&xr, g_xr);
    cudaGetSymbolAddress((void**)&wv, g_w);

    size_t smem = (size_t)SMEMF * sizeof(float);   // 92672 B -> 2 CTAs/SM
    cudaFuncSetAttribute(conv_wmma<1>, cudaFuncAttributeMaxDynamicSharedMemorySize, (int)smem);
    cudaFuncSetAttribute(conv_wmma<2>, cudaFuncAttributeMaxDynamicSharedMemorySize, (int)smem);

    scan_kernel<<<Bc, Lc>>>(tgt);
    cvt_w<<<dim3(192, 2), 256>>>(c1w, c2w);
    cvt_x<<<8192, 256>>>(x);
    conv_wmma<1><<<dim3(Lc / MT, Bc), 256, smem>>>(
        xr, wv, c1b, g1, b1, nullptr, nullptr, nullptr);
    conv_wmma<2><<<dim3(Lc / MT, Bc), 256, smem>>>(
        h1, wv + 768 * Fc, c2b, g2, b2, lw, lb, dp);
    gather_kernel<<<dim3(T / 64, Bc), 256>>>(x, out, T);
}